// round 6
// baseline (speedup 1.0000x reference)
#include <cuda_runtime.h>
#include <math.h>

// Problem dims (fixed by the reference)
#define NB 2048   // batch
#define NI 256    // inner / contraction dim j
#define NO 256    // output dim i

#define J_CH 64                   // j-chunk per smem stage
#define CX_STRIDE 68              // floats per j-pair row (32b * 2 + 4 pad)
#define NC_STRIDE 68              // floats per j-pair row (32i * 2 + 4 pad)
#define CX_ELEMS ((J_CH / 2) * CX_STRIDE)   // 2176 floats
#define NC_ELEMS ((J_CH / 2) * NC_STRIDE)   // 2176 floats
#define SMEM_FLOATS (2 * CX_ELEMS + 2 * NC_ELEMS)   // 8704 -> 34816 B

typedef unsigned long long ull;

// ---------------- packed f32x2 helpers ----------------
__device__ __forceinline__ ull ffma2(ull a, ull b, ull c) {
    ull d;
    asm("fma.rn.f32x2 %0, %1, %2, %3;" : "=l"(d) : "l"(a), "l"(b), "l"(c));
    return d;
}
__device__ __forceinline__ ull fadd2(ull a, ull b) {
    ull d;
    asm("add.rn.f32x2 %0, %1, %2;" : "=l"(d) : "l"(a), "l"(b));
    return d;
}
__device__ __forceinline__ ull fmul2(ull a, ull b) {
    ull d;
    asm("mul.rn.f32x2 %0, %1, %2;" : "=l"(d) : "l"(a), "l"(b));
    return d;
}
__device__ __forceinline__ float2 u2f(ull v) {
    float2 r;
    asm("mov.b64 {%0, %1}, %2;" : "=f"(r.x), "=f"(r.y) : "l"(v));
    return r;
}
__device__ __forceinline__ float frcp(float x) {
    float r;
    asm("rcp.approx.f32 %0, %1;" : "=f"(r) : "f"(x));
    return r;
}

// 4 j-terms fused: D=(d_j0,d_j1), E=(d_j2,d_j3).
// sum 1/d = (S.x*P.y + S.y*P.x) * rcp(P.x*P.y), S=D+E, P=D*E.
#define QCELL(acc, cA, sA, cB, sB, nA, oA, nB, oB)                     \
    do {                                                               \
        ull D_ = ffma2((cA), (nA), ffma2((sA), (oA), Q2));             \
        ull E_ = ffma2((cB), (nB), ffma2((sB), (oB), Q2));             \
        float2 S_ = u2f(fadd2(D_, E_));                                \
        float2 P_ = u2f(fmul2(D_, E_));                                \
        (acc) = fmaf(fmaf(S_.x, P_.y, S_.y * P_.x),                    \
                     frcp(P_.x * P_.y), (acc));                        \
    } while (0)

// CTA tile = 32(b) x 32(i), 256 threads, thread micro-tile 2(b) x 2(i).
// grid (64, 8) = 512 CTAs x 8 warps = 4096 warps (~27.7/SM).
__global__ __launch_bounds__(256) void photonic_fused(
        float* __restrict__ out,
        const float* __restrict__ x, const float* __restrict__ off,
        float phi0, float two_rho, ull Q2, float negK) {
    extern __shared__ float smem[];
    float* s_cx = smem;                         // [J_CH/2][CX_STRIDE]
    float* s_sx = s_cx + CX_ELEMS;
    float* s_nc = s_sx + CX_ELEMS;              // [J_CH/2][NC_STRIDE]
    float* s_so = s_nc + NC_ELEMS;

    const int t  = threadIdx.x;
    const int tx = t & 15;                      // 16 groups along b (2 b each)
    const int ty = t >> 4;                      // 16 groups along i (2 i each)
    const int b_blk = blockIdx.x * 32;
    const int i_blk = blockIdx.y * 32;

    // fill-phase coordinates
    const int jj  = t & 63;                     // j within chunk
    const int g4  = t >> 6;                     // 0..3
    const int par = jj & 1;
    const int jph = jj >> 1;                    // j-pair row

    float a00 = 0.f, a01 = 0.f, a10 = 0.f, a11 = 0.f;

    for (int chunk = 0; chunk < NI / J_CH; ++chunk) {
        const int j_base = chunk * J_CH;
        __syncthreads();   // previous chunk's reads done before overwrite

        // x-side: 32 rows x 64 j  (8 sincos / thread), coalesced gmem reads
        #pragma unroll
        for (int k = 0; k < 8; ++k) {
            int bl = g4 + k * 4;
            float s, c;
            __sincosf(phi0 + x[(b_blk + bl) * NI + j_base + jj], &s, &c);
            int idx = jph * CX_STRIDE + bl * 2 + par;
            s_cx[idx] = c;
            s_sx[idx] = s;
        }
        // o-side: 32 rows x 64 j  (8 sincos / thread)
        #pragma unroll
        for (int k = 0; k < 8; ++k) {
            int il = g4 + k * 4;
            float s, c;
            __sincosf(off[(i_blk + il) * NI + j_base + jj], &s, &c);
            int idx = jph * NC_STRIDE + il * 2 + par;
            s_nc[idx] = -two_rho * c;
            s_so[idx] =  two_rho * s;
        }
        __syncthreads();

        const float* cxb = s_cx + tx * 4;       // this thread's 2 b's (pair-interleaved)
        const float* sxb = s_sx + tx * 4;
        const float* ncb = s_nc + ty * 4;       // this thread's 2 i's
        const float* sob = s_so + ty * 4;

        #pragma unroll 4
        for (int jp = 0; jp < J_CH / 2; jp += 2) {   // 4 j per iter
            const ulonglong2 cxA = *(const ulonglong2*)(cxb + (jp    ) * CX_STRIDE);
            const ulonglong2 cxB = *(const ulonglong2*)(cxb + (jp + 1) * CX_STRIDE);
            const ulonglong2 sxA = *(const ulonglong2*)(sxb + (jp    ) * CX_STRIDE);
            const ulonglong2 sxB = *(const ulonglong2*)(sxb + (jp + 1) * CX_STRIDE);
            const ulonglong2 nA  = *(const ulonglong2*)(ncb + (jp    ) * NC_STRIDE);
            const ulonglong2 nB  = *(const ulonglong2*)(ncb + (jp + 1) * NC_STRIDE);
            const ulonglong2 oA  = *(const ulonglong2*)(sob + (jp    ) * NC_STRIDE);
            const ulonglong2 oB  = *(const ulonglong2*)(sob + (jp + 1) * NC_STRIDE);

            // (b0, i0) / (b0, i0+1)
            QCELL(a00, cxA.x, sxA.x, cxB.x, sxB.x, nA.x, oA.x, nB.x, oB.x);
            QCELL(a01, cxA.x, sxA.x, cxB.x, sxB.x, nA.y, oA.y, nB.y, oB.y);
            // (b0+1, i0) / (b0+1, i0+1)
            QCELL(a10, cxA.y, sxA.y, cxB.y, sxB.y, nA.x, oA.x, nB.x, oB.x);
            QCELL(a11, cxA.y, sxA.y, cxB.y, sxB.y, nA.y, oA.y, nB.y, oB.y);
        }
    }

    const int b0 = b_blk + tx * 2;
    const int i0 = i_blk + ty * 2;
    float2 r0, r1;
    r0.x = fmaf(negK, a00, (float)NI);
    r0.y = fmaf(negK, a01, (float)NI);
    r1.x = fmaf(negK, a10, (float)NI);
    r1.y = fmaf(negK, a11, (float)NI);
    *(float2*)(out + (b0 + 0) * NO + i0) = r0;
    *(float2*)(out + (b0 + 1) * NO + i0) = r1;
}

extern "C" void kernel_launch(void* const* d_in, const int* in_sizes, int n_in,
                              void* d_out, int out_size) {
    const float* x   = (const float*)d_in[0];   // input_matrix [2048, 256]
    const float* off = (const float*)d_in[1];   // phase_offset [256, 256]
    float* out = (float*)d_out;                 // [2048, 256]

    // Physics constants
    const double PI     = 3.14159265358979323846;
    const double RADIUS = 5e-6;
    const double KAPPA  = 0.1;
    const double N_EFF  = 3.48;
    const double LAMBDA = 1.55e-6;
    const double LOSS_A = 0.99;

    const double t   = sqrt(1.0 - KAPPA);
    const double a   = LOSS_A;
    const double rho = a * t;
    const double phi0 = fmod(2.0 * PI * N_EFF * (2.0 * PI * RADIUS) / LAMBDA, 2.0 * PI);

    const float Qc      = (float)(1.0 + rho * rho);
    const float two_rho = (float)(2.0 * rho);
    const float negK    = (float)(-(1.0 - t * t) * (1.0 - a * a));

    unsigned int qbits;
    memcpy(&qbits, &Qc, 4);
    const ull Q2 = ((ull)qbits << 32) | qbits;   // packed (Qc, Qc)

    const int smem_bytes = SMEM_FLOATS * sizeof(float);   // 34816
    cudaFuncSetAttribute(photonic_fused,
                         cudaFuncAttributeMaxDynamicSharedMemorySize, smem_bytes);

    dim3 grid(NB / 32, NO / 32);   // (64, 8) = 512 CTAs
    photonic_fused<<<grid, 256, smem_bytes>>>(out, x, off,
                                              (float)phi0, two_rho, Q2, negK);
}